// round 1
// baseline (speedup 1.0000x reference)
#include <cuda_runtime.h>

#define NB 16
#define NS 4
#define NK 11
#define NBSK (NB * NS * NK)   // 704
#define HW 16384              // 128*128

// Scratch: per-(b,s,k) heat partial and label partial. Static device global
// (no allocation).
__device__ float g_part[2 * NBSK];

__global__ void __launch_bounds__(256, 4)
keypoint_main_kernel(const float* __restrict__ cp,     // (16,4,22,128,128)
                     const float* __restrict__ heat,   // (16,11,128,128)
                     const float* __restrict__ lab)    // (16,11,11)
{
    const int bsk = blockIdx.x;          // 0..703
    const int k   = bsk % NK;
    const int bs  = bsk / NK;            // b*4+s
    const int b   = bs / NS;

    // hm map for this (b,s,k): channel index k within 22
    const float4* __restrict__ hptr =
        (const float4*)(cp + ((size_t)(bs * 22 + k) << 14));
    const float4* __restrict__ gptr =
        (const float4*)(heat + ((size_t)(b * NK + k) << 14));

    const int t = threadIdx.x;           // 0..255

    float sum = 0.0f;
    float mx  = -__int_as_float(0x7f800000); // -inf
    int   mi  = 0;

    #pragma unroll
    for (int j = 0; j < 16; j++) {
        const int v = t + j * 256;       // float4 index in [0,4096)
        const float4 h = hptr[v];
        const float4 g = gptr[v];
        float d0 = h.x - g.x, d1 = h.y - g.y, d2 = h.z - g.z, d3 = h.w - g.w;
        sum = fmaf(d0, d0, sum);
        sum = fmaf(d1, d1, sum);
        sum = fmaf(d2, d2, sum);
        sum = fmaf(d3, d3, sum);
        const int base = v << 2;
        // ascending index within thread -> strict > keeps first occurrence
        if (h.x > mx) { mx = h.x; mi = base; }
        if (h.y > mx) { mx = h.y; mi = base + 1; }
        if (h.z > mx) { mx = h.z; mi = base + 2; }
        if (h.w > mx) { mx = h.w; mi = base + 3; }
    }

    // Warp reduce (sum, argmax with lowest-index tiebreak)
    #pragma unroll
    for (int off = 16; off > 0; off >>= 1) {
        float osum = __shfl_down_sync(0xffffffffu, sum, off);
        float omx  = __shfl_down_sync(0xffffffffu, mx,  off);
        int   omi  = __shfl_down_sync(0xffffffffu, mi,  off);
        sum += osum;
        if (omx > mx || (omx == mx && omi < mi)) { mx = omx; mi = omi; }
    }

    __shared__ float ssum[8];
    __shared__ float smx[8];
    __shared__ int   smi[8];
    const int w = t >> 5, l = t & 31;
    if (l == 0) { ssum[w] = sum; smx[w] = mx; smi[w] = mi; }
    __syncthreads();

    if (t == 0) {
        #pragma unroll
        for (int w2 = 1; w2 < 8; w2++) {
            sum += ssum[w2];
            if (smx[w2] > mx || (smx[w2] == mx && smi[w2] < mi)) {
                mx = smx[w2]; mi = smi[w2];
            }
        }

        // ---- label-loss term for this (b,s,k) ----
        const float* __restrict__ lp =
            cp + ((size_t)(bs * 22 + NK + k) << 14);     // lb map, first 9 used
        const float* __restrict__ lb = lab + (size_t)(b * NK + k) * 11;

        const float gx = lb[9];
        const float gy = lb[10];
        const bool valid = (gx > 0.0f) && (gy > 0.0f) &&
                           (gx < 128.0f) && (gy < 128.0f);

        const float xf = (float)(mi >> 7);    // index // 128
        const float yf = (float)(mi & 127);   // index % 128

        const float dx = gx + lb[7] - xf - lp[7];
        const float dy = gy + lb[8] - yf - lp[8];
        const float xy_loss = dx * dx + dy * dy;

        const float c = 1.0f - mx;
        const float conf_loss = c * c;

        float cls = 0.0f;
        #pragma unroll
        for (int j = 0; j < 7; j++) {
            const float d = lp[j] - lb[j];
            cls = fmaf(d, d, cls);
        }

        g_part[bsk]        = sum;
        g_part[NBSK + bsk] = valid ? (cls + xy_loss + conf_loss) : 0.0f;
    }
}

// Deterministic final reduce: one thread per (b,s); sums 11 keypoints.
__global__ void keypoint_reduce_kernel(float* __restrict__ out)
{
    const int i = threadIdx.x;           // 0..63 = b*4+s
    if (i >= NB * NS) return;
    float h = 0.0f, lsum = 0.0f;
    #pragma unroll
    for (int k = 0; k < NK; k++) {
        h    += g_part[i * NK + k];
        lsum += g_part[NBSK + i * NK + k];
    }
    out[i]           = h;      // heat_loss (16,4)
    out[64 + i]      = lsum;   // label_loss (16,4)
}

extern "C" void kernel_launch(void* const* d_in, const int* in_sizes, int n_in,
                              void* d_out, int out_size)
{
    const float* cp   = (const float*)d_in[0]; // combined_preds
    const float* heat = (const float*)d_in[1]; // heatmaps
    const float* lab  = (const float*)d_in[2]; // labels
    float* out = (float*)d_out;

    keypoint_main_kernel<<<NBSK, 256>>>(cp, heat, lab);
    keypoint_reduce_kernel<<<1, 64>>>(out);
}